// round 10
// baseline (speedup 1.0000x reference)
#include <cuda_runtime.h>
#include <cuda_bf16.h>
#include <cstdint>

#define BB 4
#define TT 4096
#define DIN 1024
#define HH 64
#define MROWS (BB*TT)

// bf16 hi/lo split scratch
__device__ __nv_bfloat16 g_qh[(size_t)MROWS*HH], g_ql[(size_t)MROWS*HH];
__device__ __nv_bfloat16 g_kh[(size_t)MROWS*HH], g_kl[(size_t)MROWS*HH];
__device__ __nv_bfloat16 g_vth[(size_t)MROWS*HH], g_vtl[(size_t)MROWS*HH]; // [b][h][t]
// pre-converted inputs
__device__ __nv_bfloat16 g_xh[(size_t)MROWS*DIN], g_xl[(size_t)MROWS*DIN];
__device__ __nv_bfloat16 g_wh[3*HH*DIN], g_wl[3*HH*DIN];
// attention accumulators (fp32)
__device__ float g_O[(size_t)MROWS*HH];
__device__ float g_ell[MROWS];

// ---------------- helpers ----------------
__device__ __forceinline__ void mma_bf16(float* d, const uint32_t* a,
                                         uint32_t b0, uint32_t b1) {
    asm volatile(
        "mma.sync.aligned.m16n8k16.row.col.f32.bf16.bf16.f32 "
        "{%0,%1,%2,%3}, {%4,%5,%6,%7}, {%8,%9}, {%0,%1,%2,%3};"
        : "+f"(d[0]), "+f"(d[1]), "+f"(d[2]), "+f"(d[3])
        : "r"(a[0]), "r"(a[1]), "r"(a[2]), "r"(a[3]), "r"(b0), "r"(b1));
}

__device__ __forceinline__ void ldsm_x4(uint32_t& r0, uint32_t& r1,
                                        uint32_t& r2, uint32_t& r3, uint32_t a) {
    asm volatile("ldmatrix.sync.aligned.m8n8.x4.shared.b16 {%0,%1,%2,%3}, [%4];"
                 : "=r"(r0), "=r"(r1), "=r"(r2), "=r"(r3) : "r"(a));
}

__device__ __forceinline__ void split_pair(float x, float y,
                                           uint32_t& h, uint32_t& l) {
    __nv_bfloat162 hv = __floats2bfloat162_rn(x, y);
    float hx = __bfloat162float(hv.x);
    float hy = __bfloat162float(hv.y);
    __nv_bfloat162 lv = __floats2bfloat162_rn(x - hx, y - hy);
    h = *reinterpret_cast<uint32_t*>(&hv);
    l = *reinterpret_cast<uint32_t*>(&lv);
}

__device__ __forceinline__ uint32_t smem_u32(const void* p) {
    uint32_t a;
    asm("{ .reg .u64 t; cvta.to.shared.u64 t, %1; cvt.u32.u64 %0, t; }"
        : "=r"(a) : "l"(p));
    return a;
}

__device__ __forceinline__ void cpa16(uint32_t dst, const void* src) {
    asm volatile("cp.async.cg.shared.global [%0], [%1], 16;"
                 :: "r"(dst), "l"(src) : "memory");
}
#define CPA_COMMIT() asm volatile("cp.async.commit_group;" ::: "memory")
#define CPA_WAIT(N)  asm volatile("cp.async.wait_group %0;" :: "n"(N) : "memory")

__device__ __forceinline__ void redg_v2(float* p, float a, float b) {
    asm volatile("red.global.add.v2.f32 [%0], {%1, %2};"
                 :: "l"(p), "f"(a), "f"(b) : "memory");
}

#define RS 144   // smem row stride bytes

// ============================================================================
// Pre-convert + zero accumulators
// ============================================================================
__global__ __launch_bounds__(256) void convert_kernel(
    const float* __restrict__ x,
    const float* __restrict__ Wq, const float* __restrict__ Wk,
    const float* __restrict__ Wv)
{
    const size_t tid0 = (size_t)blockIdx.x * 256 + threadIdx.x;
    const size_t stride = (size_t)gridDim.x * 256;
    const size_t NX = (size_t)MROWS * DIN / 4;
    for (size_t t = tid0; t < NX; t += stride) {
        float4 v = ((const float4*)x)[t];
        uint32_t h0, l0, h1, l1;
        split_pair(v.x, v.y, h0, l0);
        split_pair(v.z, v.w, h1, l1);
        ((uint2*)g_xh)[t] = make_uint2(h0, h1);
        ((uint2*)g_xl)[t] = make_uint2(l0, l1);
    }
    const size_t NW = (size_t)HH * DIN / 4;
    for (size_t t = tid0; t < 3 * NW; t += stride) {
        const int set = (int)(t / NW);
        const size_t o = t - (size_t)set * NW;
        const float* W = (set == 0) ? Wq : (set == 1) ? Wk : Wv;
        float4 v = ((const float4*)W)[o];
        uint32_t h0, l0, h1, l1;
        split_pair(v.x, v.y, h0, l0);
        split_pair(v.z, v.w, h1, l1);
        ((uint2*)g_wh)[t] = make_uint2(h0, h1);
        ((uint2*)g_wl)[t] = make_uint2(l0, l1);
    }
    const float4 z4 = make_float4(0.f, 0.f, 0.f, 0.f);
    const size_t NO = (size_t)MROWS * HH / 4;
    for (size_t t = tid0; t < NO; t += stride) ((float4*)g_O)[t] = z4;
    for (size_t t = tid0; t < MROWS / 4; t += stride) ((float4*)g_ell)[t] = z4;
}

// ============================================================================
// Projection: grid=(128,3), 256 thr, 2 CTAs/SM, cp.async double buffer + ldsm.
// ============================================================================
#define P_XH 0
#define P_XL (128*RS)
#define P_WH (256*RS)
#define P_WL (256*RS + 64*RS)
#define PBUF (384*RS)
#define PROJ_SMEM (2*PBUF)

__global__ __launch_bounds__(256, 2) void proj_kernel(
    const float* __restrict__ bq, const float* __restrict__ bk,
    const float* __restrict__ bv)
{
    extern __shared__ char smp[];
    __shared__ float s_bias[64];
    const uint32_t sbase = smem_u32(smp);

    const int tid = threadIdx.x;
    const int wid = tid >> 5, lane = tid & 31;
    const int g = lane >> 2, tg = lane & 3;
    const int m0 = blockIdx.x * 128;
    const int my = blockIdx.y;

    const float* bias = (my == 0) ? bq : (my == 1) ? bk : bv;
    if (tid < 64) s_bias[tid] = bias[tid];

    const size_t wset = (size_t)my * HH * DIN;

    auto stage = [&](int kc, int bi) {
        const int k0 = kc * 64;
        const uint32_t bb = sbase + bi * PBUF;
#pragma unroll
        for (int u = tid; u < 3072; u += 256) {
            uint32_t dst; const void* src;
            if (u < 2048) {
                const int comp = u >> 10;
                const int idx = u & 1023;
                const int r = idx >> 3, c8 = idx & 7;
                const __nv_bfloat16* gsrc = comp ? g_xl : g_xh;
                src = gsrc + (size_t)(m0 + r) * DIN + k0 + c8 * 8;
                dst = bb + (comp ? P_XL : P_XH) + r * RS + c8 * 16;
            } else {
                const int comp = (u - 2048) >> 9;
                const int idx = (u - 2048) & 511;
                const int r = idx >> 3, c8 = idx & 7;
                const __nv_bfloat16* gsrc = comp ? g_wl : g_wh;
                src = gsrc + wset + (size_t)r * DIN + k0 + c8 * 8;
                dst = bb + (comp ? P_WL : P_WH) + r * RS + c8 * 16;
            }
            cpa16(dst, src);
        }
        CPA_COMMIT();
    };

    const uint32_t aoff = (lane & 7) * RS + ((lane >> 3) & 1) * 8 * RS
                        + ((lane >> 4) & 1) * 16;
    const uint32_t boff = (lane & 7) * RS + ((lane >> 4) & 1) * 8 * RS
                        + ((lane >> 3) & 1) * 16;

    float acc[8][4];
#pragma unroll
    for (int n = 0; n < 8; ++n)
#pragma unroll
        for (int q = 0; q < 4; ++q) acc[n][q] = 0.f;

    stage(0, 0);
    for (int kc = 0; kc < 16; ++kc) {
        CPA_WAIT(0);
        __syncthreads();
        if (kc < 15) stage(kc + 1, (kc + 1) & 1);

        const uint32_t bb = sbase + (kc & 1) * PBUF;
        const uint32_t Xh = bb + P_XH, Xl = bb + P_XL;
        const uint32_t Wh = bb + P_WH, Wl = bb + P_WL;
        const int ra = wid * 16;

#pragma unroll
        for (int ks = 0; ks < 4; ++ks) {
            uint32_t ah[4], al[4];
            ldsm_x4(ah[0], ah[1], ah[2], ah[3], Xh + ra * RS + ks * 32 + aoff);
            ldsm_x4(al[0], al[1], al[2], al[3], Xl + ra * RS + ks * 32 + aoff);
#pragma unroll
            for (int p = 0; p < 4; ++p) {
                uint32_t h0, h1, h2, h3, l0, l1, l2, l3;
                ldsm_x4(h0, h1, h2, h3, Wh + p * 16 * RS + ks * 32 + boff);
                ldsm_x4(l0, l1, l2, l3, Wl + p * 16 * RS + ks * 32 + boff);
                mma_bf16(acc[2*p],   ah, h0, h1);
                mma_bf16(acc[2*p],   al, h0, h1);
                mma_bf16(acc[2*p],   ah, l0, l1);
                mma_bf16(acc[2*p+1], ah, h2, h3);
                mma_bf16(acc[2*p+1], al, h2, h3);
                mma_bf16(acc[2*p+1], ah, l2, l3);
            }
        }
        __syncthreads();
    }

    // epilogue
    const int rA = m0 + wid * 16 + g;
    const int rB = rA + 8;
#pragma unroll
    for (int n = 0; n < 8; ++n) {
        const int col = 8 * n + 2 * tg;
        float v0 = acc[n][0] + s_bias[col];
        float v1 = acc[n][1] + s_bias[col + 1];
        float v2 = acc[n][2] + s_bias[col];
        float v3 = acc[n][3] + s_bias[col + 1];
        if (my < 2) {
            uint32_t h01, l01, h23, l23;
            split_pair(v0, v1, h01, l01);
            split_pair(v2, v3, h23, l23);
            __nv_bfloat16* oh = (my == 0) ? g_qh : g_kh;
            __nv_bfloat16* ol = (my == 0) ? g_ql : g_kl;
            *(uint32_t*)(oh + (size_t)rA * 64 + col) = h01;
            *(uint32_t*)(ol + (size_t)rA * 64 + col) = l01;
            *(uint32_t*)(oh + (size_t)rB * 64 + col) = h23;
            *(uint32_t*)(ol + (size_t)rB * 64 + col) = l23;
        } else {
            const int bA = rA >> 12, tA = rA & 4095;
            const int bB = rB >> 12, tB = rB & 4095;
            __nv_bfloat16 h;
            h = __float2bfloat16_rn(v0);
            g_vth[(size_t)(bA*64 + col  )*4096 + tA] = h;
            g_vtl[(size_t)(bA*64 + col  )*4096 + tA] = __float2bfloat16_rn(v0 - __bfloat162float(h));
            h = __float2bfloat16_rn(v1);
            g_vth[(size_t)(bA*64 + col+1)*4096 + tA] = h;
            g_vtl[(size_t)(bA*64 + col+1)*4096 + tA] = __float2bfloat16_rn(v1 - __bfloat162float(h));
            h = __float2bfloat16_rn(v2);
            g_vth[(size_t)(bB*64 + col  )*4096 + tB] = h;
            g_vtl[(size_t)(bB*64 + col  )*4096 + tB] = __float2bfloat16_rn(v2 - __bfloat162float(h));
            h = __float2bfloat16_rn(v3);
            g_vth[(size_t)(bB*64 + col+1)*4096 + tB] = h;
            g_vtl[(size_t)(bB*64 + col+1)*4096 + tB] = __float2bfloat16_rn(v3 - __bfloat162float(h));
        }
    }
}

// ============================================================================
// Attention: proj-mold. CTA = 256 thr (8 warps), i-tile = 128 rows,
// j-tile = 64, chunk = up to 8 j-tiles, double-buffered QV, 2 CTAs/SM.
// grid = 4 batches x 144 chunks. Linear softmax; RED accumulate; divide after.
// ============================================================================
#define AK_SZ (2*128*RS)                 // K hi+lo: 36864
#define AQV   (4*64*RS)                  // Qh,Ql,Vh,Vl: 36864
#define ATTN_SMEM (AK_SZ + 2*AQV)        // 110592

__global__ __launch_bounds__(256, 2) void attn_kernel()
{
    extern __shared__ char smp[];
    const uint32_t sbase = smem_u32(smp);
    const int tid = threadIdx.x;
    const int lw  = tid >> 5;            // 0..7
    const int lane = tid & 31;
    const int g  = lane >> 2, tg = lane & 3;

    const int b   = blockIdx.x & 3;
    const int cid = 143 - (blockIdx.x >> 2);   // heavy chunks first
    // group k (=chunks per i-block) spans cids [2k(k-1), 2k(k+1))
    int kk = 1;
    while (2 * kk * (kk + 1) <= cid) ++kk;
    const int off = cid - 2 * kk * (kk - 1);
    const int ib  = 4 * (kk - 1) + off / kk;   // i-block (128 rows)
    const int jc  = off % kk;
    const int jt0 = jc * 8;
    const int jt1 = min(jt0 + 8, 2 * ib + 2);
    const int i0  = ib * 128;

    const uint32_t Kb = sbase;           // Kh at 0, Kl at +128*RS

    // group 0: K tile (128 rows, hi+lo)
#pragma unroll
    for (int i = tid; i < 2048; i += 256) {
        const int comp = i >> 10;
        const int idx = i & 1023;
        const int r = idx >> 3, c8 = idx & 7;
        const __nv_bfloat16* gsrc = comp ? g_kl : g_kh;
        cpa16(Kb + comp * (128 * RS) + r * RS + c8 * 16,
              gsrc + (size_t)(b * 4096 + i0 + r) * 64 + c8 * 8);
    }
    CPA_COMMIT();

    auto stage = [&](int jt, int bi) {
        const int j0 = jt * 64;
        const uint32_t bb = sbase + AK_SZ + bi * AQV;
#pragma unroll
        for (int i = tid; i < 2048; i += 256) {
            const int comp = i >> 9;     // 0=Qh,1=Ql,2=Vh,3=Vl
            const int idx = i & 511;
            const int r = idx >> 3, c8 = idx & 7;
            const void* src;
            if (comp == 0)
                src = g_qh + (size_t)(b * 4096 + j0 + r) * 64 + c8 * 8;
            else if (comp == 1)
                src = g_ql + (size_t)(b * 4096 + j0 + r) * 64 + c8 * 8;
            else if (comp == 2)
                src = g_vth + (size_t)(b * 64 + r) * 4096 + j0 + c8 * 8;
            else
                src = g_vtl + (size_t)(b * 64 + r) * 4096 + j0 + c8 * 8;
            cpa16(bb + comp * (64 * RS) + r * RS + c8 * 16, src);
        }
        CPA_COMMIT();
    };

    const uint32_t aoff = (lane & 7) * RS + ((lane >> 3) & 1) * 8 * RS
                        + ((lane >> 4) & 1) * 16;
    const uint32_t boff = (lane & 7) * RS + ((lane >> 4) & 1) * 8 * RS
                        + ((lane >> 3) & 1) * 16;
    const int rowA = i0 + lw * 16 + g;

    float o[8][4];
#pragma unroll
    for (int n = 0; n < 8; ++n)
#pragma unroll
        for (int q = 0; q < 4; ++q) o[n][q] = 0.f;
    float ellA = 0.f, ellB = 0.f;

    stage(jt0, jt0 & 1);
    for (int jt = jt0; jt < jt1; ++jt) {
        const int j0 = jt * 64;
        CPA_WAIT(0);
        __syncthreads();
        if (jt + 1 < jt1) stage(jt + 1, (jt + 1) & 1);

        // warp-uniform skip: whole 16-row strip above this j-tile -> all masked
        const bool active = (j0 <= i0 + lw * 16 + 15);
        if (active) {
            const uint32_t bb = sbase + AK_SZ + (jt & 1) * AQV;
            const uint32_t Qh = bb, Ql = bb + 64 * RS;
            const uint32_t Vh = bb + 128 * RS, Vl = bb + 192 * RS;

            // ---- S = K . Q^T ----
            float s[8][4];
#pragma unroll
            for (int n = 0; n < 8; ++n)
#pragma unroll
                for (int q = 0; q < 4; ++q) s[n][q] = 0.f;

#pragma unroll
            for (int ks = 0; ks < 4; ++ks) {
                uint32_t khf[4], klf[4];
                ldsm_x4(khf[0], khf[1], khf[2], khf[3],
                        Kb + (lw * 16) * RS + ks * 32 + aoff);
                ldsm_x4(klf[0], klf[1], klf[2], klf[3],
                        Kb + 128 * RS + (lw * 16) * RS + ks * 32 + aoff);
#pragma unroll
                for (int p = 0; p < 4; ++p) {
                    uint32_t h0, h1, h2, h3, l0, l1, l2, l3;
                    ldsm_x4(h0, h1, h2, h3, Qh + p * 16 * RS + ks * 32 + boff);
                    ldsm_x4(l0, l1, l2, l3, Ql + p * 16 * RS + ks * 32 + boff);
                    mma_bf16(s[2*p],   khf, h0, h1);
                    mma_bf16(s[2*p],   klf, h0, h1);
                    mma_bf16(s[2*p],   khf, l0, l1);
                    mma_bf16(s[2*p+1], khf, h2, h3);
                    mma_bf16(s[2*p+1], klf, h2, h3);
                    mma_bf16(s[2*p+1], khf, l2, l3);
                }
            }

            // ---- fused per kt: exp(S) -> pack -> O += P_kt . V_kt ----
            const bool diag = (j0 + 63 > rowA);
#pragma unroll
            for (int kt = 0; kt < 4; ++kt) {
                uint32_t pha[4], pla[4];
#pragma unroll
                for (int h = 0; h < 2; ++h) {
                    const int n = 2 * kt + h;
                    float p0 = __expf(s[n][0]);
                    float p1 = __expf(s[n][1]);
                    float p2 = __expf(s[n][2]);
                    float p3 = __expf(s[n][3]);
                    if (diag) {
                        const int col = j0 + 8 * n + 2 * tg;
                        if (col     > rowA)     p0 = 0.f;
                        if (col + 1 > rowA)     p1 = 0.f;
                        if (col     > rowA + 8) p2 = 0.f;
                        if (col + 1 > rowA + 8) p3 = 0.f;
                    }
                    ellA += p0 + p1;
                    ellB += p2 + p3;
                    uint32_t h01, l01, h23, l23;
                    split_pair(p0, p1, h01, l01);
                    split_pair(p2, p3, h23, l23);
                    if (h == 0) {
                        pha[0] = h01; pha[1] = h23;
                        pla[0] = l01; pla[1] = l23;
                    } else {
                        pha[2] = h01; pha[3] = h23;
                        pla[2] = l01; pla[3] = l23;
                    }
                }
#pragma unroll
                for (int p = 0; p < 4; ++p) {
                    uint32_t h0, h1, h2, h3, l0, l1, l2, l3;
                    ldsm_x4(h0, h1, h2, h3, Vh + p * 16 * RS + kt * 32 + boff);
                    ldsm_x4(l0, l1, l2, l3, Vl + p * 16 * RS + kt * 32 + boff);
                    mma_bf16(o[2*p],   pha, h0, h1);
                    mma_bf16(o[2*p],   pla, h0, h1);
                    mma_bf16(o[2*p],   pha, l0, l1);
                    mma_bf16(o[2*p+1], pha, h2, h3);
                    mma_bf16(o[2*p+1], pla, h2, h3);
                    mma_bf16(o[2*p+1], pha, l2, l3);
                }
            }
        }
        __syncthreads();   // all reads of this buffer done before it is restaged
    }

    // ---- epilogue: vector red accumulate O, scalar ell ----
    ellA += __shfl_xor_sync(0xffffffffu, ellA, 1);
    ellA += __shfl_xor_sync(0xffffffffu, ellA, 2);
    ellB += __shfl_xor_sync(0xffffffffu, ellB, 1);
    ellB += __shfl_xor_sync(0xffffffffu, ellB, 2);
    if (tg == 0) {
        atomicAdd(&g_ell[b * 4096 + rowA],     ellA);
        atomicAdd(&g_ell[b * 4096 + rowA + 8], ellB);
    }
    float* OA = g_O + (size_t)(b * 4096 + rowA) * 64;
    float* OB = OA + 8 * 64;
#pragma unroll
    for (int n = 0; n < 8; ++n) {
        const int col = 8 * n + 2 * tg;
        redg_v2(OA + col, o[n][0], o[n][1]);
        redg_v2(OB + col, o[n][2], o[n][3]);
    }
}

// ============================================================================
// Divide: out = O / ell
// ============================================================================
__global__ __launch_bounds__(256) void divide_kernel(float* __restrict__ out)
{
    const size_t tid0 = (size_t)blockIdx.x * 256 + threadIdx.x;
    const size_t stride = (size_t)gridDim.x * 256;
    const size_t N = (size_t)MROWS * HH / 4;
    for (size_t u = tid0; u < N; u += stride) {
        const size_t m = u >> 4;
        const float inv = 1.0f / g_ell[m];
        float4 v = ((const float4*)g_O)[u];
        v.x *= inv; v.y *= inv; v.z *= inv; v.w *= inv;
        ((float4*)out)[u] = v;
    }
}

// ============================================================================
extern "C" void kernel_launch(void* const* d_in, const int* in_sizes, int n_in,
                              void* d_out, int out_size)
{
    const float* x  = (const float*)d_in[0];
    const float* Wq = (const float*)d_in[1];
    const float* bq = (const float*)d_in[2];
    const float* Wk = (const float*)d_in[3];
    const float* bk = (const float*)d_in[4];
    const float* Wv = (const float*)d_in[5];
    const float* bv = (const float*)d_in[6];
    float* out = (float*)d_out;

    cudaFuncSetAttribute(proj_kernel, cudaFuncAttributeMaxDynamicSharedMemorySize, PROJ_SMEM);
    cudaFuncSetAttribute(attn_kernel, cudaFuncAttributeMaxDynamicSharedMemorySize, ATTN_SMEM);

    convert_kernel<<<1024, 256>>>(x, Wq, Wk, Wv);
    proj_kernel<<<dim3(128, 3), 256, PROJ_SMEM>>>(bq, bk, bv);
    attn_kernel<<<4 * 144, 256, ATTN_SMEM>>>();
    divide_kernel<<<1024, 256>>>(out);
}